// round 13
// baseline (speedup 1.0000x reference)
#include <cuda_runtime.h>
#include <cuda_fp16.h>
#include <cstdint>

// ============================================================================
// MixResidualBlockC, R13: bisected fusion.
//  fused12: stage1 (A=xt, B=W1) -> sincos -> hbuf(smem)
//           stage2 (A=hbuf, B=W2) -> sincos -> g_h2 (GLOBAL, R11 layout)
//  gemm3:   R11's proven MODE-3 kernel (A=g_h2 + xt tail, B=W3) -> out
// ============================================================================

#define NPIX 4096
#define NB 16

// fused12 smem map
#define HSTR 1040                     // hbuf row stride (512 fp16 + 8 pad)
#define HBY (128 * HSTR)              // 133120
#define F_BOFF HBY
#define F_BCH (256 * 80)              // 20480
#define F_AOFF (F_BOFF + 2 * F_BCH)   // 174080
#define F_ACH (128 * 80)              // 10240
#define SMEM_F (F_AOFF + 2 * F_ACH)   // 194560

// gemm3 (R11) smem map
#define S3_STRIDE 144
#define S3_PLANE (128 * S3_STRIDE)    // 18432
#define S3_BUFSZ (2 * S3_PLANE)       // 36864
#define SMEM_G 73728

// -------------------- device scratch --------------------------------------
__device__ float g_mix[NB * 8];
__device__ float g_b1[NB * 256], g_b2[NB * 256], g_b3[NB * 256];
__device__ __half g_w1[NB * 256 * 256];
__device__ __half g_w2[NB * 256 * 512];
__device__ __half g_w3[NB * 256 * 768];
__device__ __half g_xt[(size_t)NB * NPIX * 256];
__device__ __half g_h2[(size_t)NB * NPIX * 512];

// -------------------- PTX helpers ------------------------------------------
__device__ __forceinline__ uint32_t smem_u32(const void* p) {
    uint32_t a;
    asm("{ .reg .u64 t; cvta.to.shared.u64 t, %1; cvt.u32.u64 %0, t; }" : "=r"(a) : "l"(p));
    return a;
}
__device__ __forceinline__ void cpa16(uint32_t dst, const void* src) {
    asm volatile("cp.async.cg.shared.global [%0], [%1], 16;" :: "r"(dst), "l"(src));
}
__device__ __forceinline__ void cpa_commit() { asm volatile("cp.async.commit_group;"); }

__device__ __forceinline__ void ldsm_x4(uint32_t* r, uint32_t addr) {
    asm volatile("ldmatrix.sync.aligned.m8n8.x4.shared.b16 {%0,%1,%2,%3}, [%4];"
                 : "=r"(r[0]), "=r"(r[1]), "=r"(r[2]), "=r"(r[3]) : "r"(addr));
}
__device__ __forceinline__ void mma_f16(float* d, const uint32_t* a,
                                        uint32_t b0, uint32_t b1) {
    asm volatile(
        "mma.sync.aligned.m16n8k16.row.col.f32.f16.f16.f32 "
        "{%0,%1,%2,%3}, {%4,%5,%6,%7}, {%8,%9}, {%0,%1,%2,%3};"
        : "+f"(d[0]), "+f"(d[1]), "+f"(d[2]), "+f"(d[3])
        : "r"(a[0]), "r"(a[1]), "r"(a[2]), "r"(a[3]), "r"(b0), "r"(b1));
}
__device__ __forceinline__ uint32_t packh2(float a, float b) {
    __half h0 = __float2half_rn(a), h1 = __float2half_rn(b);
    return (uint32_t)__half_as_ushort(h0) | ((uint32_t)__half_as_ushort(h1) << 16);
}

// -------------------- K0: mixing coefficients ------------------------------
__global__ void mix_kernel(const float* __restrict__ lat, const float* __restrict__ wd,
                           const float* __restrict__ bd) {
    int t = threadIdx.x;
    if (t < 128) {
        int b = t >> 3, m = t & 7;
        float a = bd[m];
        const float* lp = lat + b * 512;
        const float* wp = wd + m * 512;
        #pragma unroll 8
        for (int l = 0; l < 512; l++) a += lp[l] * wp[l];
        g_mix[t] = a;
    }
}

// -------------------- K1: weight mixing -> fp16 ----------------------------
__global__ void prep_kernel(const float* __restrict__ kin, const float* __restrict__ kmid,
                            const float* __restrict__ kout, const float* __restrict__ ksh,
                            const float* __restrict__ bin, const float* __restrict__ bmid,
                            const float* __restrict__ bout, const float* __restrict__ bsh) {
    __shared__ float smix[128];
    if (threadIdx.x < 128) smix[threadIdx.x] = g_mix[threadIdx.x];
    __syncthreads();
    int p = blockIdx.x * 256 + threadIdx.x;
    float v[8];

    if (p < 65536) {
        #pragma unroll
        for (int m = 0; m < 8; m++) v[m] = kin[m * 65536 + p];
        #pragma unroll
        for (int b = 0; b < NB; b++) {
            float a = 0.f;
            #pragma unroll
            for (int m = 0; m < 8; m++) a += smix[b * 8 + m] * v[m];
            g_w1[b * 65536 + p] = __float2half_rn(a);
        }
    } else if (p < 196608) {
        int q = p - 65536;
        #pragma unroll
        for (int m = 0; m < 8; m++) v[m] = kmid[m * 131072 + q];
        #pragma unroll
        for (int b = 0; b < NB; b++) {
            float a = 0.f;
            #pragma unroll
            for (int m = 0; m < 8; m++) a += smix[b * 8 + m] * v[m];
            g_w2[b * 131072 + q] = __float2half_rn(a);
        }
    } else if (p < 327680) {
        int q = p - 196608;
        int o = q >> 9, i = q & 511;
        #pragma unroll
        for (int m = 0; m < 8; m++) v[m] = kout[m * 131072 + q];
        int di = o * 768 + i;
        #pragma unroll
        for (int b = 0; b < NB; b++) {
            float a = 0.f;
            #pragma unroll
            for (int m = 0; m < 8; m++) a += smix[b * 8 + m] * v[m];
            g_w3[b * 196608 + di] = __float2half_rn(a);
        }
    } else if (p < 393216) {
        int q = p - 327680;
        int o = q >> 8, i = q & 255;
        #pragma unroll
        for (int m = 0; m < 8; m++) v[m] = ksh[m * 65536 + q];
        int di = o * 768 + 512 + i;
        #pragma unroll
        for (int b = 0; b < NB; b++) {
            float a = 0.f;
            #pragma unroll
            for (int m = 0; m < 8; m++) a += smix[b * 8 + m] * v[m];
            g_w3[b * 196608 + di] = __float2half_rn(a);
        }
    } else if (p < 393472) {
        int r = p - 393216;
        float vi[8], vm[8], vo[8];
        #pragma unroll
        for (int m = 0; m < 8; m++) {
            vi[m] = bin[m * 256 + r];
            vm[m] = bmid[m * 256 + r];
            vo[m] = bout[m * 256 + r] + bsh[m * 256 + r];
        }
        #pragma unroll
        for (int b = 0; b < NB; b++) {
            float a1 = 0.f, a2 = 0.f, a3 = 0.f;
            #pragma unroll
            for (int m = 0; m < 8; m++) {
                float mx = smix[b * 8 + m];
                a1 += mx * vi[m]; a2 += mx * vm[m]; a3 += mx * vo[m];
            }
            g_b1[b * 256 + r] = a1;
            g_b2[b * 256 + r] = a2;
            g_b3[b * 256 + r] = a3;
        }
    }
}

// -------------------- K2: x transpose  x[b,c,p] -> xt[b,p,c] (fp16) --------
__global__ void xt_kernel(const float* __restrict__ x) {
    __shared__ float ts[32][33];
    int b = blockIdx.z, p0 = blockIdx.x * 32, c0 = blockIdx.y * 32;
    const float* src = x + ((size_t)b * 256 + c0) * NPIX + p0;
    for (int r = threadIdx.y; r < 32; r += 8)
        ts[r][threadIdx.x] = src[(size_t)r * NPIX + threadIdx.x];
    __syncthreads();
    int lane = threadIdx.x;
    for (int pr = threadIdx.y; pr < 32; pr += 8) {
        size_t di = ((size_t)b * NPIX + p0 + pr) * 256 + c0 + lane;
        g_xt[di] = __float2half_rn(ts[lane][pr]);
    }
}

// -------------------- fused stages 1+2 --------------------------------------
__global__ void __launch_bounds__(256, 1)
fused12_kernel() {
    extern __shared__ __align__(16) char dsm[];
    const uint32_t sb = smem_u32(dsm);
    __shared__ float sb1[256], sb2[256];

    const int tid = threadIdx.x;
    const int lane = tid & 31;
    const int wid = tid >> 5;
    const int warp_m = wid & 1;       // 0..1 (64 px)
    const int warp_n = wid >> 1;      // 0..3 (64 ch)
    const int b = blockIdx.y;
    const int p0 = blockIdx.x * 128;

    const __half* Xt = g_xt + (size_t)b * NPIX * 256;
    const __half* W1 = g_w1 + (size_t)b * 65536;
    const __half* W2 = g_w2 + (size_t)b * 131072;

    sb1[tid] = g_b1[b * 256 + tid];
    sb2[tid] = g_b2[b * 256 + tid];

    const int a_off = (warp_m * 64 + (lane & 15)) * 80 + ((lane >> 4) & 1) * 16;
    const int h_off = (warp_m * 64 + (lane & 15)) * HSTR + ((lane >> 4) & 1) * 16;
    const int b_off = (warp_n * 64 + (lane & 15)) * 80 + ((lane >> 4) & 1) * 16;
    const int lg = lane >> 2;
    const int l2 = (lane & 3) * 2;

    float acc[4][8][4];

    auto copyA = [&](int acol, int buf) {
        #pragma unroll
        for (int j = 0; j < 2; j++) {
            int u = tid + j * 256;
            int r = u >> 2, c = u & 3;
            cpa16(sb + F_AOFF + buf * F_ACH + r * 80 + c * 16,
                  Xt + (size_t)(p0 + r) * 256 + acol + c * 8);
        }
    };
    auto copyB = [&](const __half* Bg, int Kd, int k0, int buf) {
        #pragma unroll
        for (int j = 0; j < 4; j++) {
            int u = tid + j * 256;
            int r = u >> 2, c = u & 3;
            cpa16(sb + F_BOFF + buf * F_BCH + r * 80 + c * 16,
                  Bg + (size_t)r * Kd + k0 + c * 8);
        }
    };
    auto zero_acc = [&]() {
        #pragma unroll
        for (int i = 0; i < 4; i++)
            #pragma unroll
            for (int j = 0; j < 8; j++)
                #pragma unroll
                for (int q = 0; q < 4; q++) acc[i][j][q] = 0.f;
    };
    auto compute_ks = [&](bool a_from_h, int hcolb, int buf, int ks) {
        uint32_t fA[4][4], fB[4][4];
        #pragma unroll
        for (int mi = 0; mi < 4; mi++) {
            uint32_t addr = a_from_h
                ? sb + h_off + mi * (16 * HSTR) + hcolb + ks * 32
                : sb + F_AOFF + buf * F_ACH + a_off + mi * (16 * 80) + ks * 32;
            ldsm_x4(fA[mi], addr);
        }
        #pragma unroll
        for (int np = 0; np < 4; np++)
            ldsm_x4(fB[np], sb + F_BOFF + buf * F_BCH + b_off + np * (16 * 80) + ks * 32);
        #pragma unroll
        for (int mi = 0; mi < 4; mi++)
            #pragma unroll
            for (int np = 0; np < 4; np++) {
                mma_f16(acc[mi][np * 2 + 0], fA[mi], fB[np][0], fB[np][2]);
                mma_f16(acc[mi][np * 2 + 1], fA[mi], fB[np][1], fB[np][3]);
            }
    };

    // ============ stage 1: K=256, A = xt streamed ==========================
    zero_acc();
    copyA(0, 0); copyB(W1, 256, 0, 0); cpa_commit();
    copyA(32, 1); copyB(W1, 256, 32, 1); cpa_commit();
    for (int ch = 0; ch < 8; ch++) {
        const int buf = ch & 1;
        if (ch + 1 < 8) asm volatile("cp.async.wait_group 1;" ::: "memory");
        else            asm volatile("cp.async.wait_group 0;" ::: "memory");
        __syncthreads();
        compute_ks(false, 0, buf, 0);
        compute_ks(false, 0, buf, 1);
        if (ch + 2 < 8) {
            __syncthreads();
            copyA((ch + 2) * 32, buf); copyB(W1, 256, (ch + 2) * 32, buf); cpa_commit();
        }
    }
    __syncthreads();

    // epilogue 1: sincos -> hbuf
    #pragma unroll
    for (int mi = 0; mi < 4; mi++) {
        #pragma unroll
        for (int ni = 0; ni < 8; ni++) {
            const int ch = warp_n * 64 + ni * 8 + l2;
            const float b0 = sb1[ch], b1 = sb1[ch + 1];
            #pragma unroll
            for (int h = 0; h < 2; h++) {
                const int pxl = warp_m * 64 + mi * 16 + lg + h * 8;
                float v0 = acc[mi][ni][h * 2 + 0] + b0;
                float v1 = acc[mi][ni][h * 2 + 1] + b1;
                float s0, c0, s1, c1;
                __sincosf(v0, &s0, &c0);
                __sincosf(v1, &s1, &c1);
                char* base = dsm + pxl * HSTR + ch * 2;
                *(uint32_t*)(base)       = packh2(s0, s1);
                *(uint32_t*)(base + 512) = packh2(c0, c1);
            }
        }
    }
    __syncthreads();

    // ============ stage 2: K=512, A = hbuf =================================
    zero_acc();
    copyB(W2, 512, 0, 0); cpa_commit();
    copyB(W2, 512, 32, 1); cpa_commit();
    for (int ch = 0; ch < 16; ch++) {
        const int buf = ch & 1;
        if (ch + 1 < 16) asm volatile("cp.async.wait_group 1;" ::: "memory");
        else             asm volatile("cp.async.wait_group 0;" ::: "memory");
        __syncthreads();
        compute_ks(true, ch * 64, buf, 0);
        compute_ks(true, ch * 64, buf, 1);
        if (ch + 2 < 16) {
            __syncthreads();
            copyB(W2, 512, (ch + 2) * 32, buf); cpa_commit();
        }
    }

    // epilogue 2: sincos -> g_h2 (GLOBAL, R11-proven layout)
    #pragma unroll
    for (int mi = 0; mi < 4; mi++) {
        const int pix = p0 + warp_m * 64 + mi * 16 + lg;
        const size_t r0 = ((size_t)b * NPIX + pix) * 512;
        const size_t r1 = r0 + 8 * 512;
        #pragma unroll
        for (int ni = 0; ni < 8; ni++) {
            const int chg = warp_n * 64 + ni * 8 + l2;
            const float b0 = sb2[chg], b1 = sb2[chg + 1];
            #pragma unroll
            for (int h = 0; h < 2; h++) {
                const size_t row = h ? r1 : r0;
                float v0 = acc[mi][ni][h * 2 + 0] + b0;
                float v1 = acc[mi][ni][h * 2 + 1] + b1;
                float s0, c0, s1, c1;
                __sincosf(v0, &s0, &c0);
                __sincosf(v1, &s1, &c1);
                *(uint32_t*)(g_h2 + row + chg)       = packh2(s0, s1);
                *(uint32_t*)(g_h2 + row + chg + 256) = packh2(c0, c1);
            }
        }
    }
}

// -------------------- gemm3 (R11 verbatim, MODE 3) --------------------------
__global__ void __launch_bounds__(256, 2)
gemm3_kernel(float* __restrict__ out) {
    constexpr int K = 768;
    constexpr int NCH = K / 64;

    extern __shared__ __align__(16) char dsm[];
    const uint32_t sbase = smem_u32(dsm);
    __shared__ float sbias[128];

    const int tid = threadIdx.x;
    const int lane = tid & 31;
    const int wid = tid >> 5;
    const int warp_m = wid & 1;
    const int warp_n = wid >> 1;
    const int b = blockIdx.z;
    const int p0 = blockIdx.x * 128;
    const int cg0 = blockIdx.y * 128;

    const __half* A = g_h2 + (size_t)b * NPIX * 512;
    const __half* B = g_w3 + (size_t)b * 196608;
    const float* bias = g_b3 + b * 256;
    const __half* Xt = g_xt + (size_t)b * NPIX * 256;

    if (tid < 128) sbias[tid] = bias[cg0 + tid];

    auto copy_chunk = [&](int ch, int buf) {
        const int k0 = ch * 64;
        const uint32_t bb = sbase + buf * S3_BUFSZ;
        const __half* pA = A;
        int acol = k0, arow = 512;
        if (k0 >= 512) { pA = Xt; acol = k0 - 512; arow = 256; }
        #pragma unroll
        for (int j = 0; j < 8; j++) {
            int u = tid + j * 256;
            int plane = u >> 10;
            int r = (u >> 3) & 127;
            int c = u & 7;
            uint32_t dst = bb + plane * S3_PLANE + r * S3_STRIDE + c * 16;
            const __half* src;
            if (plane == 0) src = pA + (size_t)(p0 + r) * arow + acol + c * 8;
            else            src = B + (size_t)(cg0 + r) * K + k0 + c * 8;
            cpa16(dst, src);
        }
        cpa_commit();
    };

    const int a_row_off = (warp_m * 64 + (lane & 15)) * S3_STRIDE + ((lane >> 4) & 1) * 16;
    const int b_row_off = (warp_n * 32 + (lane & 15)) * S3_STRIDE + ((lane >> 4) & 1) * 16;

    float acc[4][4][4];
    #pragma unroll
    for (int i = 0; i < 4; i++)
        #pragma unroll
        for (int j = 0; j < 4; j++)
            #pragma unroll
            for (int q = 0; q < 4; q++) acc[i][j][q] = 0.f;

    copy_chunk(0, 0);
    copy_chunk(1, 1);

    for (int it = 0; it < NCH; it++) {
        const int buf = it & 1;
        if (it + 1 < NCH) asm volatile("cp.async.wait_group 1;" ::: "memory");
        else              asm volatile("cp.async.wait_group 0;" ::: "memory");
        __syncthreads();
        const uint32_t bb = sbase + buf * S3_BUFSZ;

        #pragma unroll
        for (int ks = 0; ks < 4; ks++) {
            uint32_t fA[4][4], fB[2][4];
            #pragma unroll
            for (int mi = 0; mi < 4; mi++)
                ldsm_x4(fA[mi], bb + a_row_off + mi * (16 * S3_STRIDE) + ks * 32);
            #pragma unroll
            for (int np = 0; np < 2; np++)
                ldsm_x4(fB[np], bb + S3_PLANE + b_row_off + np * (16 * S3_STRIDE) + ks * 32);
            #pragma unroll
            for (int mi = 0; mi < 4; mi++)
                #pragma unroll
                for (int np = 0; np < 2; np++) {
                    mma_f16(acc[mi][np * 2 + 0], fA[mi], fB[np][0], fB[np][2]);
                    mma_f16(acc[mi][np * 2 + 1], fA[mi], fB[np][1], fB[np][3]);
                }
        }
        if (it + 2 < NCH) {
            __syncthreads();
            copy_chunk(it + 2, buf);
        }
    }

    const int lg = lane >> 2;
    const int l2 = (lane & 3) * 2;

    float* smf = (float*)dsm;
    __syncthreads();
    #pragma unroll
    for (int mi = 0; mi < 4; mi++) {
        const int pxl0 = warp_m * 64 + mi * 16 + lg;
        #pragma unroll
        for (int ni = 0; ni < 4; ni++) {
            const int chl = warp_n * 32 + ni * 8 + l2;
            const float b0 = sbias[chl], b1 = sbias[chl + 1];
            smf[pxl0 * 132 + chl]           = acc[mi][ni][0] + b0;
            smf[pxl0 * 132 + chl + 1]       = acc[mi][ni][1] + b1;
            smf[(pxl0 + 8) * 132 + chl]     = acc[mi][ni][2] + b0;
            smf[(pxl0 + 8) * 132 + chl + 1] = acc[mi][ni][3] + b1;
        }
    }
    __syncthreads();
    const int ch = tid >> 1;
    const int pxh = (tid & 1) * 64;
    float* orow = out + ((size_t)b * 256 + cg0 + ch) * NPIX + p0 + pxh;
    #pragma unroll
    for (int g = 0; g < 16; g++) {
        float4 v;
        v.x = smf[(pxh + g * 4 + 0) * 132 + ch];
        v.y = smf[(pxh + g * 4 + 1) * 132 + ch];
        v.z = smf[(pxh + g * 4 + 2) * 132 + ch];
        v.w = smf[(pxh + g * 4 + 3) * 132 + ch];
        *(float4*)(orow + g * 4) = v;
    }
}

// -------------------- launch ------------------------------------------------
extern "C" void kernel_launch(void* const* d_in, const int* in_sizes, int n_in,
                              void* d_out, int out_size) {
    const float* x           = (const float*)d_in[0];
    const float* lat         = (const float*)d_in[1];
    const float* k_in_mix    = (const float*)d_in[2];
    const float* k_mid_mix   = (const float*)d_in[3];
    const float* k_out_mix   = (const float*)d_in[4];
    const float* k_short_mix = (const float*)d_in[5];
    const float* b_in_mix    = (const float*)d_in[6];
    const float* b_mid_mix   = (const float*)d_in[7];
    const float* b_out_mix   = (const float*)d_in[8];
    const float* b_short_mix = (const float*)d_in[9];
    const float* w_dyna      = (const float*)d_in[10];
    const float* b_dyna      = (const float*)d_in[11];
    float* out = (float*)d_out;

    cudaFuncSetAttribute(fused12_kernel, cudaFuncAttributeMaxDynamicSharedMemorySize, SMEM_F);
    cudaFuncSetAttribute(gemm3_kernel, cudaFuncAttributeMaxDynamicSharedMemorySize, SMEM_G);

    mix_kernel<<<1, 128>>>(lat, w_dyna, b_dyna);
    prep_kernel<<<1537, 256>>>(k_in_mix, k_mid_mix, k_out_mix, k_short_mix,
                               b_in_mix, b_mid_mix, b_out_mix, b_short_mix);
    xt_kernel<<<dim3(128, 8, 16), dim3(32, 8)>>>(x);
    fused12_kernel<<<dim3(32, 16), 256, SMEM_F>>>();
    gemm3_kernel<<<dim3(32, 2, 16), 256, SMEM_G>>>(out);
}

// round 14
// speedup vs baseline: 1.1032x; 1.1032x over previous
#include <cuda_runtime.h>
#include <cuda_fp16.h>
#include <cstdint>

// ============================================================================
// MixResidualBlockC via warp-level fp16 mma.sync (pure fp16 inputs, fp32 acc):
//   stage1: h1 = sincos(W1[256,256] @ xt)           (pixel-major fp16)
//   stage2: h2 = sincos(W2[256,512] @ h1)
//   stage3: out = W3[256,768] @ [h2 ; xt] + b3      (W3 = [k_out | k_short])
// R14: R11 config (8 warps, warp tile 64x32, BK=64) + 3-buffer cp.async
// pipeline -> single __syncthreads per chunk. 2 CTAs/SM (110.6KB smem).
// ============================================================================

#define NPIX 4096
#define NB 16
#define STRIDE 144                     // bytes per 64-fp16 smem row (padded)
#define PLANE (128 * STRIDE)           // 18432 B per plane tile
#define BUFSZ (2 * PLANE)              // A | B = 36864 B
#define SMEM_G (3 * BUFSZ)             // 110592 B (3 buffers)

// -------------------- device scratch --------------------------------------
__device__ float g_mix[NB * 8];
__device__ float g_b1[NB * 256], g_b2[NB * 256], g_b3[NB * 256];
__device__ __half g_w1[NB * 256 * 256];
__device__ __half g_w2[NB * 256 * 512];
__device__ __half g_w3[NB * 256 * 768];
__device__ __half g_xt[(size_t)NB * NPIX * 256];
__device__ __half g_h1[(size_t)NB * NPIX * 512];
__device__ __half g_h2[(size_t)NB * NPIX * 512];

// -------------------- PTX helpers (all arch-portable) ----------------------
__device__ __forceinline__ uint32_t smem_u32(const void* p) {
    uint32_t a;
    asm("{ .reg .u64 t; cvta.to.shared.u64 t, %1; cvt.u32.u64 %0, t; }" : "=r"(a) : "l"(p));
    return a;
}
__device__ __forceinline__ void cpa16(uint32_t dst, const void* src) {
    asm volatile("cp.async.cg.shared.global [%0], [%1], 16;" :: "r"(dst), "l"(src));
}
__device__ __forceinline__ void cpa_commit() { asm volatile("cp.async.commit_group;"); }

__device__ __forceinline__ void ldsm_x4(uint32_t* r, uint32_t addr) {
    asm volatile("ldmatrix.sync.aligned.m8n8.x4.shared.b16 {%0,%1,%2,%3}, [%4];"
                 : "=r"(r[0]), "=r"(r[1]), "=r"(r[2]), "=r"(r[3]) : "r"(addr));
}
__device__ __forceinline__ void mma_f16(float* d, const uint32_t* a,
                                        uint32_t b0, uint32_t b1) {
    asm volatile(
        "mma.sync.aligned.m16n8k16.row.col.f32.f16.f16.f32 "
        "{%0,%1,%2,%3}, {%4,%5,%6,%7}, {%8,%9}, {%0,%1,%2,%3};"
        : "+f"(d[0]), "+f"(d[1]), "+f"(d[2]), "+f"(d[3])
        : "r"(a[0]), "r"(a[1]), "r"(a[2]), "r"(a[3]), "r"(b0), "r"(b1));
}
__device__ __forceinline__ uint32_t packh2(float a, float b) {
    __half h0 = __float2half_rn(a), h1 = __float2half_rn(b);
    return (uint32_t)__half_as_ushort(h0) | ((uint32_t)__half_as_ushort(h1) << 16);
}

// -------------------- K0: mixing coefficients ------------------------------
__global__ void mix_kernel(const float* __restrict__ lat, const float* __restrict__ wd,
                           const float* __restrict__ bd) {
    int t = threadIdx.x;
    if (t < 128) {
        int b = t >> 3, m = t & 7;
        float a = bd[m];
        const float* lp = lat + b * 512;
        const float* wp = wd + m * 512;
        #pragma unroll 8
        for (int l = 0; l < 512; l++) a += lp[l] * wp[l];
        g_mix[t] = a;
    }
}

// -------------------- K1: weight mixing -> fp16 ----------------------------
__global__ void prep_kernel(const float* __restrict__ kin, const float* __restrict__ kmid,
                            const float* __restrict__ kout, const float* __restrict__ ksh,
                            const float* __restrict__ bin, const float* __restrict__ bmid,
                            const float* __restrict__ bout, const float* __restrict__ bsh) {
    __shared__ float smix[128];
    if (threadIdx.x < 128) smix[threadIdx.x] = g_mix[threadIdx.x];
    __syncthreads();
    int p = blockIdx.x * 256 + threadIdx.x;
    float v[8];

    if (p < 65536) {  // w1 (k_in)
        #pragma unroll
        for (int m = 0; m < 8; m++) v[m] = kin[m * 65536 + p];
        #pragma unroll
        for (int b = 0; b < NB; b++) {
            float a = 0.f;
            #pragma unroll
            for (int m = 0; m < 8; m++) a += smix[b * 8 + m] * v[m];
            g_w1[b * 65536 + p] = __float2half_rn(a);
        }
    } else if (p < 196608) {  // w2 (k_mid)
        int q = p - 65536;
        #pragma unroll
        for (int m = 0; m < 8; m++) v[m] = kmid[m * 131072 + q];
        #pragma unroll
        for (int b = 0; b < NB; b++) {
            float a = 0.f;
            #pragma unroll
            for (int m = 0; m < 8; m++) a += smix[b * 8 + m] * v[m];
            g_w2[b * 131072 + q] = __float2half_rn(a);
        }
    } else if (p < 327680) {  // w3 k_out part: cols [0,512)
        int q = p - 196608;
        int o = q >> 9, i = q & 511;
        #pragma unroll
        for (int m = 0; m < 8; m++) v[m] = kout[m * 131072 + q];
        int di = o * 768 + i;
        #pragma unroll
        for (int b = 0; b < NB; b++) {
            float a = 0.f;
            #pragma unroll
            for (int m = 0; m < 8; m++) a += smix[b * 8 + m] * v[m];
            g_w3[b * 196608 + di] = __float2half_rn(a);
        }
    } else if (p < 393216) {  // w3 k_short part: cols [512,768)
        int q = p - 327680;
        int o = q >> 8, i = q & 255;
        #pragma unroll
        for (int m = 0; m < 8; m++) v[m] = ksh[m * 65536 + q];
        int di = o * 768 + 512 + i;
        #pragma unroll
        for (int b = 0; b < NB; b++) {
            float a = 0.f;
            #pragma unroll
            for (int m = 0; m < 8; m++) a += smix[b * 8 + m] * v[m];
            g_w3[b * 196608 + di] = __float2half_rn(a);
        }
    } else if (p < 393472) {  // biases
        int r = p - 393216;
        float vi[8], vm[8], vo[8];
        #pragma unroll
        for (int m = 0; m < 8; m++) {
            vi[m] = bin[m * 256 + r];
            vm[m] = bmid[m * 256 + r];
            vo[m] = bout[m * 256 + r] + bsh[m * 256 + r];
        }
        #pragma unroll
        for (int b = 0; b < NB; b++) {
            float a1 = 0.f, a2 = 0.f, a3 = 0.f;
            #pragma unroll
            for (int m = 0; m < 8; m++) {
                float mx = smix[b * 8 + m];
                a1 += mx * vi[m]; a2 += mx * vm[m]; a3 += mx * vo[m];
            }
            g_b1[b * 256 + r] = a1;
            g_b2[b * 256 + r] = a2;
            g_b3[b * 256 + r] = a3;
        }
    }
}

// -------------------- K2: x transpose  x[b,c,p] -> xt[b,p,c] (fp16) --------
__global__ void xt_kernel(const float* __restrict__ x) {
    __shared__ float ts[32][33];
    int b = blockIdx.z, p0 = blockIdx.x * 32, c0 = blockIdx.y * 32;
    const float* src = x + ((size_t)b * 256 + c0) * NPIX + p0;
    for (int r = threadIdx.y; r < 32; r += 8)
        ts[r][threadIdx.x] = src[(size_t)r * NPIX + threadIdx.x];
    __syncthreads();
    int lane = threadIdx.x;
    for (int pr = threadIdx.y; pr < 32; pr += 8) {
        size_t di = ((size_t)b * NPIX + p0 + pr) * 256 + c0 + lane;
        g_xt[di] = __float2half_rn(ts[lane][pr]);
    }
}

// -------------------- GEMM stage (pure fp16 mma.sync) ----------------------
// CTA 128x128, 8 warps (2x4), warp tile 64x32, BK=64, 3-buffer pipeline.
template <int MODE>  // 1,2,3
__global__ void __launch_bounds__(256, 2)
gemm_stage(float* __restrict__ out) {
    constexpr int K = (MODE == 1) ? 256 : (MODE == 2) ? 512 : 768;
    constexpr int NCH = K / 64;
    constexpr int AROW = (MODE == 1) ? 256 : 512;

    extern __shared__ __align__(16) char dsm[];
    const uint32_t sbase = smem_u32(dsm);
    __shared__ float sbias[128];

    const int tid = threadIdx.x;
    const int lane = tid & 31;
    const int wid = tid >> 5;
    const int warp_m = wid & 1;       // 0..1  (64 px each)
    const int warp_n = wid >> 1;      // 0..3  (32 ch each)
    const int b = blockIdx.z;
    const int p0 = blockIdx.x * 128;
    const int cg0 = blockIdx.y * 128;

    const __half *A, *B;
    const float* bias;
    if constexpr (MODE == 1) {
        A = g_xt + (size_t)b * NPIX * 256;
        B = g_w1 + (size_t)b * 65536;
        bias = g_b1 + b * 256;
    } else if constexpr (MODE == 2) {
        A = g_h1 + (size_t)b * NPIX * 512;
        B = g_w2 + (size_t)b * 131072;
        bias = g_b2 + b * 256;
    } else {
        A = g_h2 + (size_t)b * NPIX * 512;
        B = g_w3 + (size_t)b * 196608;
        bias = g_b3 + b * 256;
    }
    const __half* Xt = g_xt + (size_t)b * NPIX * 256;  // MODE3 tail

    if (tid < 128) sbias[tid] = bias[cg0 + tid];

    // ---- chunk copier: 2048 x 16B (A | B planes, 128 rows x 8 units) ------
    auto copy_chunk = [&](int ch, int buf) {
        const int k0 = ch * 64;
        const uint32_t bb = sbase + buf * BUFSZ;
        const __half* pA = A;
        int acol = k0, arow = AROW;
        if (MODE == 3 && k0 >= 512) { pA = Xt; acol = k0 - 512; arow = 256; }
        #pragma unroll
        for (int j = 0; j < 8; j++) {
            int u = tid + j * 256;
            int plane = u >> 10;          // 0 A, 1 B
            int r = (u >> 3) & 127;
            int c = u & 7;
            uint32_t dst = bb + plane * PLANE + r * STRIDE + c * 16;
            const __half* src;
            if (plane == 0) src = pA + (size_t)(p0 + r) * arow + acol + c * 8;
            else            src = B + (size_t)(cg0 + r) * K + k0 + c * 8;
            cpa16(dst, src);
        }
        cpa_commit();
    };

    // ---- ldmatrix lane address offsets ----
    const int a_row_off = (warp_m * 64 + (lane & 15)) * STRIDE + ((lane >> 4) & 1) * 16;
    const int b_row_off = (warp_n * 32 + (lane & 15)) * STRIDE + ((lane >> 4) & 1) * 16;

    float acc[4][4][4];
    #pragma unroll
    for (int i = 0; i < 4; i++)
        #pragma unroll
        for (int j = 0; j < 4; j++)
            #pragma unroll
            for (int q = 0; q < 4; q++) acc[i][j][q] = 0.f;

    // ---- 3-buffer pipeline: prefetch depth 2, ONE barrier per chunk -------
    copy_chunk(0, 0);
    copy_chunk(1, 1);

    for (int it = 0; it < NCH; it++) {
        const int buf = it % 3;
        if (it + 1 < NCH) asm volatile("cp.async.wait_group 1;" ::: "memory");
        else              asm volatile("cp.async.wait_group 0;" ::: "memory");
        __syncthreads();   // copies for buf visible; also: all warps done it-1
        const uint32_t bb = sbase + buf * BUFSZ;

        #pragma unroll
        for (int ks = 0; ks < 4; ks++) {
            uint32_t fA[4][4], fB[2][4];
            #pragma unroll
            for (int mi = 0; mi < 4; mi++)
                ldsm_x4(fA[mi], bb + a_row_off + mi * (16 * STRIDE) + ks * 32);
            #pragma unroll
            for (int np = 0; np < 2; np++)
                ldsm_x4(fB[np], bb + PLANE + b_row_off + np * (16 * STRIDE) + ks * 32);
            #pragma unroll
            for (int mi = 0; mi < 4; mi++)
                #pragma unroll
                for (int np = 0; np < 2; np++) {
                    mma_f16(acc[mi][np * 2 + 0], fA[mi], fB[np][0], fB[np][2]);
                    mma_f16(acc[mi][np * 2 + 1], fA[mi], fB[np][1], fB[np][3]);
                }
        }
        // target buf (it+2)%3 was last read at chunk it-1; the barrier at the
        // top of THIS iteration guarantees every warp finished chunk it-1.
        if (it + 2 < NCH) copy_chunk(it + 2, (it + 2) % 3);
    }

    // ---- epilogue -----------------------------------------------------------
    const int lg = lane >> 2;          // row-in-group 0..7
    const int l2 = (lane & 3) * 2;     // col pair

    if constexpr (MODE != 3) {
        __half* H = (MODE == 1) ? g_h1 : g_h2;
        #pragma unroll
        for (int mi = 0; mi < 4; mi++) {
            const int pix = p0 + warp_m * 64 + mi * 16 + lg;
            const size_t r0 = ((size_t)b * NPIX + pix) * 512;
            const size_t r1 = r0 + 8 * 512;
            #pragma unroll
            for (int ni = 0; ni < 4; ni++) {
                const int chl = warp_n * 32 + ni * 8 + l2;   // local 0..127
                const int chg = cg0 + chl;                   // global 0..255
                const float b0 = sbias[chl], b1 = sbias[chl + 1];
                #pragma unroll
                for (int h = 0; h < 2; h++) {
                    const size_t row = h ? r1 : r0;
                    float v0 = acc[mi][ni][h * 2 + 0] + b0;
                    float v1 = acc[mi][ni][h * 2 + 1] + b1;
                    float s0, c0, s1, c1;
                    __sincosf(v0, &s0, &c0);
                    __sincosf(v1, &s1, &c1);
                    *(uint32_t*)(H + row + chg)       = packh2(s0, s1);
                    *(uint32_t*)(H + row + chg + 256) = packh2(c0, c1);
                }
            }
        }
    } else {
        // stage smem [128 px][132] fp32 then coalesced channel-major writes
        float* smf = (float*)dsm;
        __syncthreads();               // all buffer reads done before reuse
        #pragma unroll
        for (int mi = 0; mi < 4; mi++) {
            const int pxl0 = warp_m * 64 + mi * 16 + lg;
            #pragma unroll
            for (int ni = 0; ni < 4; ni++) {
                const int chl = warp_n * 32 + ni * 8 + l2;
                const float b0 = sbias[chl], b1 = sbias[chl + 1];
                smf[pxl0 * 132 + chl]           = acc[mi][ni][0] + b0;
                smf[pxl0 * 132 + chl + 1]       = acc[mi][ni][1] + b1;
                smf[(pxl0 + 8) * 132 + chl]     = acc[mi][ni][2] + b0;
                smf[(pxl0 + 8) * 132 + chl + 1] = acc[mi][ni][3] + b1;
            }
        }
        __syncthreads();
        const int ch = tid >> 1;           // 0..127
        const int pxh = (tid & 1) * 64;
        float* orow = out + ((size_t)b * 256 + cg0 + ch) * NPIX + p0 + pxh;
        #pragma unroll
        for (int g = 0; g < 16; g++) {
            float4 v;
            v.x = smf[(pxh + g * 4 + 0) * 132 + ch];
            v.y = smf[(pxh + g * 4 + 1) * 132 + ch];
            v.z = smf[(pxh + g * 4 + 2) * 132 + ch];
            v.w = smf[(pxh + g * 4 + 3) * 132 + ch];
            *(float4*)(orow + g * 4) = v;
        }
    }
}

// -------------------- launch ------------------------------------------------
extern "C" void kernel_launch(void* const* d_in, const int* in_sizes, int n_in,
                              void* d_out, int out_size) {
    const float* x           = (const float*)d_in[0];
    const float* lat         = (const float*)d_in[1];
    const float* k_in_mix    = (const float*)d_in[2];
    const float* k_mid_mix   = (const float*)d_in[3];
    const float* k_out_mix   = (const float*)d_in[4];
    const float* k_short_mix = (const float*)d_in[5];
    const float* b_in_mix    = (const float*)d_in[6];
    const float* b_mid_mix   = (const float*)d_in[7];
    const float* b_out_mix   = (const float*)d_in[8];
    const float* b_short_mix = (const float*)d_in[9];
    const float* w_dyna      = (const float*)d_in[10];
    const float* b_dyna      = (const float*)d_in[11];
    float* out = (float*)d_out;

    cudaFuncSetAttribute(gemm_stage<1>, cudaFuncAttributeMaxDynamicSharedMemorySize, SMEM_G);
    cudaFuncSetAttribute(gemm_stage<2>, cudaFuncAttributeMaxDynamicSharedMemorySize, SMEM_G);
    cudaFuncSetAttribute(gemm_stage<3>, cudaFuncAttributeMaxDynamicSharedMemorySize, SMEM_G);

    mix_kernel<<<1, 128>>>(lat, w_dyna, b_dyna);
    prep_kernel<<<1537, 256>>>(k_in_mix, k_mid_mix, k_out_mix, k_short_mix,
                               b_in_mix, b_mid_mix, b_out_mix, b_short_mix);
    xt_kernel<<<dim3(128, 8, 16), dim3(32, 8)>>>(x);
    gemm_stage<1><<<dim3(32, 2, 16), 256, SMEM_G>>>(out);
    gemm_stage<2><<<dim3(32, 2, 16), 256, SMEM_G>>>(out);
    gemm_stage<3><<<dim3(32, 2, 16), 256, SMEM_G>>>(out);
}

// round 16
// speedup vs baseline: 1.1327x; 1.0267x over previous
#include <cuda_runtime.h>
#include <cuda_fp16.h>
#include <cstdint>

// ============================================================================
// MixResidualBlockC via warp-level fp16 mma.sync (pure fp16 inputs, fp32 acc):
//   stage1: h1 = sincos(W1[256,256] @ xt)           (pixel-major fp16)
//   stage2: h2 = sincos(W2[256,512] @ h1)
//   stage3: out = W3[256,768] @ [h2 ; xt] + b3      (W3 = [k_out | k_short])
// R16: R15 mbarrier pipeline FIXED: cp.async.mbarrier.arrive.NOINC (default
// form increments expected count -> barrier never flips -> R15 deadlock).
// CTA 128x128, 8 warps (2x4), warp tile 64x32, BK=64, 3 buffers, 2 CTAs/SM.
// ============================================================================

#define NPIX 4096
#define NB 16
#define STRIDE 144                     // bytes per 64-fp16 smem row (padded)
#define PLANE (128 * STRIDE)           // 18432 B per plane tile
#define BUFSZ (2 * PLANE)              // A | B = 36864 B
#define SMEM_G (3 * BUFSZ)             // 110592 B (3 buffers)

// -------------------- device scratch --------------------------------------
__device__ float g_mix[NB * 8];
__device__ float g_b1[NB * 256], g_b2[NB * 256], g_b3[NB * 256];
__device__ __half g_w1[NB * 256 * 256];
__device__ __half g_w2[NB * 256 * 512];
__device__ __half g_w3[NB * 256 * 768];
__device__ __half g_xt[(size_t)NB * NPIX * 256];
__device__ __half g_h1[(size_t)NB * NPIX * 512];
__device__ __half g_h2[(size_t)NB * NPIX * 512];

// -------------------- PTX helpers (all arch-portable) ----------------------
__device__ __forceinline__ uint32_t smem_u32(const void* p) {
    uint32_t a;
    asm("{ .reg .u64 t; cvta.to.shared.u64 t, %1; cvt.u32.u64 %0, t; }" : "=r"(a) : "l"(p));
    return a;
}
__device__ __forceinline__ void cpa16(uint32_t dst, const void* src) {
    asm volatile("cp.async.cg.shared.global [%0], [%1], 16;" :: "r"(dst), "l"(src));
}
__device__ __forceinline__ void mbar_init(uint32_t a, uint32_t cnt) {
    asm volatile("mbarrier.init.shared.b64 [%0], %1;" :: "r"(a), "r"(cnt) : "memory");
}
__device__ __forceinline__ void mbar_arrive(uint32_t a) {
    asm volatile("mbarrier.arrive.shared.b64 _, [%0];" :: "r"(a) : "memory");
}
__device__ __forceinline__ void cpa_arrive_noinc(uint32_t a) {
    asm volatile("cp.async.mbarrier.arrive.noinc.shared::cta.b64 [%0];" :: "r"(a) : "memory");
}
__device__ __forceinline__ void mbar_wait_acq(uint32_t a, uint32_t parity) {
    asm volatile(
        "{\n\t.reg .pred P;\n"
        "W_%=:\n\t"
        "mbarrier.try_wait.parity.acquire.cta.shared::cta.b64 P, [%0], %1, 0x989680;\n\t"
        "@!P bra W_%=;\n\t}"
        :: "r"(a), "r"(parity) : "memory");
}
__device__ __forceinline__ void mbar_wait_rel(uint32_t a, uint32_t parity) {
    asm volatile(
        "{\n\t.reg .pred P;\n"
        "W_%=:\n\t"
        "mbarrier.try_wait.parity.relaxed.cta.shared::cta.b64 P, [%0], %1, 0x989680;\n\t"
        "@!P bra W_%=;\n\t}"
        :: "r"(a), "r"(parity) : "memory");
}
__device__ __forceinline__ void ldsm_x4(uint32_t* r, uint32_t addr) {
    asm volatile("ldmatrix.sync.aligned.m8n8.x4.shared.b16 {%0,%1,%2,%3}, [%4];"
                 : "=r"(r[0]), "=r"(r[1]), "=r"(r[2]), "=r"(r[3]) : "r"(addr));
}
__device__ __forceinline__ void mma_f16(float* d, const uint32_t* a,
                                        uint32_t b0, uint32_t b1) {
    asm volatile(
        "mma.sync.aligned.m16n8k16.row.col.f32.f16.f16.f32 "
        "{%0,%1,%2,%3}, {%4,%5,%6,%7}, {%8,%9}, {%0,%1,%2,%3};"
        : "+f"(d[0]), "+f"(d[1]), "+f"(d[2]), "+f"(d[3])
        : "r"(a[0]), "r"(a[1]), "r"(a[2]), "r"(a[3]), "r"(b0), "r"(b1));
}
__device__ __forceinline__ uint32_t packh2(float a, float b) {
    __half h0 = __float2half_rn(a), h1 = __float2half_rn(b);
    return (uint32_t)__half_as_ushort(h0) | ((uint32_t)__half_as_ushort(h1) << 16);
}

// -------------------- K0: mixing coefficients ------------------------------
__global__ void mix_kernel(const float* __restrict__ lat, const float* __restrict__ wd,
                           const float* __restrict__ bd) {
    int t = threadIdx.x;
    if (t < 128) {
        int b = t >> 3, m = t & 7;
        float a = bd[m];
        const float* lp = lat + b * 512;
        const float* wp = wd + m * 512;
        #pragma unroll 8
        for (int l = 0; l < 512; l++) a += lp[l] * wp[l];
        g_mix[t] = a;
    }
}

// -------------------- K1: weight mixing -> fp16 ----------------------------
__global__ void prep_kernel(const float* __restrict__ kin, const float* __restrict__ kmid,
                            const float* __restrict__ kout, const float* __restrict__ ksh,
                            const float* __restrict__ bin, const float* __restrict__ bmid,
                            const float* __restrict__ bout, const float* __restrict__ bsh) {
    __shared__ float smix[128];
    if (threadIdx.x < 128) smix[threadIdx.x] = g_mix[threadIdx.x];
    __syncthreads();
    int p = blockIdx.x * 256 + threadIdx.x;
    float v[8];

    if (p < 65536) {  // w1 (k_in)
        #pragma unroll
        for (int m = 0; m < 8; m++) v[m] = kin[m * 65536 + p];
        #pragma unroll
        for (int b = 0; b < NB; b++) {
            float a = 0.f;
            #pragma unroll
            for (int m = 0; m < 8; m++) a += smix[b * 8 + m] * v[m];
            g_w1[b * 65536 + p] = __float2half_rn(a);
        }
    } else if (p < 196608) {  // w2 (k_mid)
        int q = p - 65536;
        #pragma unroll
        for (int m = 0; m < 8; m++) v[m] = kmid[m * 131072 + q];
        #pragma unroll
        for (int b = 0; b < NB; b++) {
            float a = 0.f;
            #pragma unroll
            for (int m = 0; m < 8; m++) a += smix[b * 8 + m] * v[m];
            g_w2[b * 131072 + q] = __float2half_rn(a);
        }
    } else if (p < 327680) {  // w3 k_out part: cols [0,512)
        int q = p - 196608;
        int o = q >> 9, i = q & 511;
        #pragma unroll
        for (int m = 0; m < 8; m++) v[m] = kout[m * 131072 + q];
        int di = o * 768 + i;
        #pragma unroll
        for (int b = 0; b < NB; b++) {
            float a = 0.f;
            #pragma unroll
            for (int m = 0; m < 8; m++) a += smix[b * 8 + m] * v[m];
            g_w3[b * 196608 + di] = __float2half_rn(a);
        }
    } else if (p < 393216) {  // w3 k_short part: cols [512,768)
        int q = p - 327680;
        int o = q >> 8, i = q & 255;
        #pragma unroll
        for (int m = 0; m < 8; m++) v[m] = ksh[m * 65536 + q];
        int di = o * 768 + 512 + i;
        #pragma unroll
        for (int b = 0; b < NB; b++) {
            float a = 0.f;
            #pragma unroll
            for (int m = 0; m < 8; m++) a += smix[b * 8 + m] * v[m];
            g_w3[b * 196608 + di] = __float2half_rn(a);
        }
    } else if (p < 393472) {  // biases
        int r = p - 393216;
        float vi[8], vm[8], vo[8];
        #pragma unroll
        for (int m = 0; m < 8; m++) {
            vi[m] = bin[m * 256 + r];
            vm[m] = bmid[m * 256 + r];
            vo[m] = bout[m * 256 + r] + bsh[m * 256 + r];
        }
        #pragma unroll
        for (int b = 0; b < NB; b++) {
            float a1 = 0.f, a2 = 0.f, a3 = 0.f;
            #pragma unroll
            for (int m = 0; m < 8; m++) {
                float mx = smix[b * 8 + m];
                a1 += mx * vi[m]; a2 += mx * vm[m]; a3 += mx * vo[m];
            }
            g_b1[b * 256 + r] = a1;
            g_b2[b * 256 + r] = a2;
            g_b3[b * 256 + r] = a3;
        }
    }
}

// -------------------- K2: x transpose  x[b,c,p] -> xt[b,p,c] (fp16) --------
__global__ void xt_kernel(const float* __restrict__ x) {
    __shared__ float ts[32][33];
    int b = blockIdx.z, p0 = blockIdx.x * 32, c0 = blockIdx.y * 32;
    const float* src = x + ((size_t)b * 256 + c0) * NPIX + p0;
    for (int r = threadIdx.y; r < 32; r += 8)
        ts[r][threadIdx.x] = src[(size_t)r * NPIX + threadIdx.x];
    __syncthreads();
    int lane = threadIdx.x;
    for (int pr = threadIdx.y; pr < 32; pr += 8) {
        size_t di = ((size_t)b * NPIX + p0 + pr) * 256 + c0 + lane;
        g_xt[di] = __float2half_rn(ts[lane][pr]);
    }
}

// -------------------- GEMM stage (pure fp16 mma.sync) ----------------------
// CTA 128x128, 8 warps (2x4), warp tile 64x32, BK=64, mbarrier pipeline.
template <int MODE>  // 1,2,3
__global__ void __launch_bounds__(256, 2)
gemm_stage(float* __restrict__ out) {
    constexpr int K = (MODE == 1) ? 256 : (MODE == 2) ? 512 : 768;
    constexpr int NCH = K / 64;
    constexpr int AROW = (MODE == 1) ? 256 : 512;

    extern __shared__ __align__(16) char dsm[];
    const uint32_t sbase = smem_u32(dsm);
    __shared__ float sbias[128];
    __shared__ __align__(8) unsigned long long s_full[3], s_empty[3];

    const int tid = threadIdx.x;
    const int lane = tid & 31;
    const int wid = tid >> 5;
    const int warp_m = wid & 1;       // 0..1  (64 px each)
    const int warp_n = wid >> 1;      // 0..3  (32 ch each)
    const int b = blockIdx.z;
    const int p0 = blockIdx.x * 128;
    const int cg0 = blockIdx.y * 128;

    const __half *A, *B;
    const float* bias;
    if constexpr (MODE == 1) {
        A = g_xt + (size_t)b * NPIX * 256;
        B = g_w1 + (size_t)b * 65536;
        bias = g_b1 + b * 256;
    } else if constexpr (MODE == 2) {
        A = g_h1 + (size_t)b * NPIX * 512;
        B = g_w2 + (size_t)b * 131072;
        bias = g_b2 + b * 256;
    } else {
        A = g_h2 + (size_t)b * NPIX * 512;
        B = g_w3 + (size_t)b * 196608;
        bias = g_b3 + b * 256;
    }
    const __half* Xt = g_xt + (size_t)b * NPIX * 256;  // MODE3 tail

    const uint32_t mb_full = smem_u32(s_full);
    const uint32_t mb_empty = smem_u32(s_empty);
    if (tid == 0) {
        #pragma unroll
        for (int s = 0; s < 3; s++) {
            mbar_init(mb_full + s * 8, 256);   // one noinc arrive per thread
            mbar_init(mb_empty + s * 8, 8);    // one arrive per warp
        }
    }
    if (tid < 128) sbias[tid] = bias[cg0 + tid];
    __syncthreads();

    // ---- chunk copier: this thread's 8 x 16B share -------------------------
    auto copy_chunk = [&](int ch, int buf) {
        const int k0 = ch * 64;
        const uint32_t bb = sbase + buf * BUFSZ;
        const __half* pA = A;
        int acol = k0, arow = AROW;
        if (MODE == 3 && k0 >= 512) { pA = Xt; acol = k0 - 512; arow = 256; }
        #pragma unroll
        for (int j = 0; j < 8; j++) {
            int u = tid + j * 256;
            int plane = u >> 10;          // 0 A, 1 B
            int r = (u >> 3) & 127;
            int c = u & 7;
            uint32_t dst = bb + plane * PLANE + r * STRIDE + c * 16;
            const __half* src;
            if (plane == 0) src = pA + (size_t)(p0 + r) * arow + acol + c * 8;
            else            src = B + (size_t)(cg0 + r) * K + k0 + c * 8;
            cpa16(dst, src);
        }
    };

    // ---- ldmatrix lane address offsets ----
    const int a_row_off = (warp_m * 64 + (lane & 15)) * STRIDE + ((lane >> 4) & 1) * 16;
    const int b_row_off = (warp_n * 32 + (lane & 15)) * STRIDE + ((lane >> 4) & 1) * 16;

    float acc[4][4][4];
    #pragma unroll
    for (int i = 0; i < 4; i++)
        #pragma unroll
        for (int j = 0; j < 4; j++)
            #pragma unroll
            for (int q = 0; q < 4; q++) acc[i][j][q] = 0.f;

    // ---- prologue: fill buffers 0 and 1 ----
    copy_chunk(0, 0); cpa_arrive_noinc(mb_full + 0 * 8);
    copy_chunk(1, 1); cpa_arrive_noinc(mb_full + 1 * 8);

    // parity bitmasks: bit s = next wait parity for that stage's barrier
    uint32_t fph = 0u;       // full: all stages start waiting parity 0
    uint32_t eph = 4u;       // empty: stage2 first wait passes on fresh barrier

    for (int it = 0; it < NCH; it++) {
        const int s = it % 3;
        mbar_wait_acq(mb_full + s * 8, (fph >> s) & 1u);
        fph ^= 1u << s;
        const uint32_t bb = sbase + s * BUFSZ;

        #pragma unroll
        for (int ks = 0; ks < 4; ks++) {
            uint32_t fA[4][4], fB[2][4];
            #pragma unroll
            for (int mi = 0; mi < 4; mi++)
                ldsm_x4(fA[mi], bb + a_row_off + mi * (16 * STRIDE) + ks * 32);
            #pragma unroll
            for (int np = 0; np < 2; np++)
                ldsm_x4(fB[np], bb + PLANE + b_row_off + np * (16 * STRIDE) + ks * 32);
            #pragma unroll
            for (int mi = 0; mi < 4; mi++)
                #pragma unroll
                for (int np = 0; np < 2; np++) {
                    mma_f16(acc[mi][np * 2 + 0], fA[mi], fB[np][0], fB[np][2]);
                    mma_f16(acc[mi][np * 2 + 1], fA[mi], fB[np][1], fB[np][3]);
                }
        }
        if (lane == 0) mbar_arrive(mb_empty + s * 8);   // warp done reading s

        if (it + 2 < NCH) {
            const int t = (it + 2) % 3;
            mbar_wait_rel(mb_empty + t * 8, (eph >> t) & 1u);
            eph ^= 1u << t;
            copy_chunk(it + 2, t);
            cpa_arrive_noinc(mb_full + t * 8);
        }
    }

    // ---- epilogue -----------------------------------------------------------
    const int lg = lane >> 2;          // row-in-group 0..7
    const int l2 = (lane & 3) * 2;     // col pair

    if constexpr (MODE != 3) {
        __half* H = (MODE == 1) ? g_h1 : g_h2;
        #pragma unroll
        for (int mi = 0; mi < 4; mi++) {
            const int pix = p0 + warp_m * 64 + mi * 16 + lg;
            const size_t r0 = ((size_t)b * NPIX + pix) * 512;
            const size_t r1 = r0 + 8 * 512;
            #pragma unroll
            for (int ni = 0; ni < 4; ni++) {
                const int chl = warp_n * 32 + ni * 8 + l2;   // local 0..127
                const int chg = cg0 + chl;                   // global 0..255
                const float b0 = sbias[chl], b1 = sbias[chl + 1];
                #pragma unroll
                for (int h = 0; h < 2; h++) {
                    const size_t row = h ? r1 : r0;
                    float v0 = acc[mi][ni][h * 2 + 0] + b0;
                    float v1 = acc[mi][ni][h * 2 + 1] + b1;
                    float s0, c0, s1, c1;
                    __sincosf(v0, &s0, &c0);
                    __sincosf(v1, &s1, &c1);
                    *(uint32_t*)(H + row + chg)       = packh2(s0, s1);
                    *(uint32_t*)(H + row + chg + 256) = packh2(c0, c1);
                }
            }
        }
    } else {
        // stage smem [128 px][132] fp32 then coalesced channel-major writes
        float* smf = (float*)dsm;
        __syncthreads();               // all buffer reads done before reuse
        #pragma unroll
        for (int mi = 0; mi < 4; mi++) {
            const int pxl0 = warp_m * 64 + mi * 16 + lg;
            #pragma unroll
            for (int ni = 0; ni < 4; ni++) {
                const int chl = warp_n * 32 + ni * 8 + l2;
                const float b0 = sbias[chl], b1 = sbias[chl + 1];
                smf[pxl0 * 132 + chl]           = acc[mi][ni][0] + b0;
                smf[pxl0 * 132 + chl + 1]       = acc[mi][ni][1] + b1;
                smf[(pxl0 + 8) * 132 + chl]     = acc[mi][ni][2] + b0;
                smf[(pxl0 + 8) * 132 + chl + 1] = acc[mi][ni][3] + b1;
            }
        }
        __syncthreads();
        const int ch = tid >> 1;           // 0..127
        const int pxh = (tid & 1) * 64;
        float* orow = out + ((size_t)b * 256 + cg0 + ch) * NPIX + p0 + pxh;
        #pragma unroll
        for (int g = 0; g < 16; g++) {
            float4 v;
            v.x = smf[(pxh + g * 4 + 0) * 132 + ch];
            v.y = smf[(pxh + g * 4 + 1) * 132 + ch];
            v.z = smf[(pxh + g * 4 + 2) * 132 + ch];
            v.w = smf[(pxh + g * 4 + 3) * 132 + ch];
            *(float4*)(orow + g * 4) = v;
        }
    }
}

// -------------------- launch ------------------------------------------------
extern "C" void kernel_launch(void* const* d_in, const int* in_sizes, int n_in,
                              void* d_out, int out_size) {
    const float* x           = (const float*)d_in[0];
    const float* lat         = (const float*)d_in[1];
    const float* k_in_mix    = (const float*)d_in[2];
    const float* k_mid_mix   = (const float*)d_in[3];
    const float* k_out_mix   = (const float*)d_in[4];
    const float* k_short_mix = (const float*)d_in[5];
    const float* b_in_mix    = (const float*)d_in[6];
    const float* b_mid_mix   = (const float*)d_in[7];
    const float* b_out_mix   = (const float*)d_in[8];
    const float* b_short_mix = (const float*)d_in[9];
    const float* w_dyna      = (const float*)d_in[10];
    const float* b_dyna      = (const float*)d_in[11];
    float* out = (float*)d_out;

    cudaFuncSetAttribute(gemm_stage<1>, cudaFuncAttributeMaxDynamicSharedMemorySize, SMEM_G);
    cudaFuncSetAttribute(gemm_stage<2>, cudaFuncAttributeMaxDynamicSharedMemorySize, SMEM_G);
    cudaFuncSetAttribute(gemm_stage<3>, cudaFuncAttributeMaxDynamicSharedMemorySize, SMEM_G);

    mix_kernel<<<1, 128>>>(lat, w_dyna, b_dyna);
    prep_kernel<<<1537, 256>>>(k_in_mix, k_mid_mix, k_out_mix, k_short_mix,
                               b_in_mix, b_mid_mix, b_out_mix, b_short_mix);
    xt_kernel<<<dim3(128, 8, 16), dim3(32, 8)>>>(x);
    gemm_stage<1><<<dim3(32, 2, 16), 256, SMEM_G>>>(out);
    gemm_stage<2><<<dim3(32, 2, 16), 256, SMEM_G>>>(out);
    gemm_stage<3><<<dim3(32, 2, 16), 256, SMEM_G>>>(out);
}